// round 11
// baseline (speedup 1.0000x reference)
#include <cuda_runtime.h>
#include <cstdint>
#include <math.h>

#define N_DRUGS 4000
#define N_GENES 4264
#define NNODES  8264
#define IN_DIM  1613
#define DIM1    1340
#define DIM2    920
#define DIM3    740
#define N_REL   4
#define N_EDGES 100000
#define NSEG    (NNODES * N_REL)

#define MPAD 8320
#define KP1  1664            // 13*128
#define KP2  1408            // 11*128
#define KP3  1024            // 8*128
#define KC1  (5 * KP1)       // 8320
#define KC2  (5 * KP2)       // 7040
#define NP1  1344            // 21*64
#define NP2  960             // 15*64
#define NP3  768             // 12*64
#define QMAXF 32512.0f

// ---------------- scratch ----------------
__device__ float         g_Xf[(size_t)MPAD * KC1];
__device__ signed char   g_Xq1[(size_t)MPAD * KC1];
__device__ unsigned char g_Xq2[(size_t)MPAD * KC1];
__device__ signed char   g_W1q1[(size_t)NP1 * KC1];
__device__ unsigned char g_W1q2[(size_t)NP1 * KC1];
__device__ float         g_A1[(size_t)NNODES * DIM1];
__device__ float         g_A1f[(size_t)MPAD * KC2];
__device__ signed char   g_A1q1[(size_t)MPAD * KC2];
__device__ unsigned char g_A1q2[(size_t)MPAD * KC2];
__device__ signed char   g_W2q1[(size_t)NP2 * KC2];
__device__ unsigned char g_W2q2[(size_t)NP2 * KC2];
__device__ float         g_A2f[(size_t)MPAD * KP3];
__device__ signed char   g_A2q1[(size_t)MPAD * KP3];
__device__ unsigned char g_A2q2[(size_t)MPAD * KP3];
__device__ signed char   g_W3q1[(size_t)NP3 * KP3];
__device__ unsigned char g_W3q2[(size_t)NP3 * KP3];
__device__ float g_amaxX[MPAD];
__device__ float g_amaxA1[MPAD];
__device__ float g_amaxA2[MPAD];
__device__ float g_cmax1[NP1];
__device__ float g_cmax2[NP2];
__device__ float g_cmax3[NP3];
__device__ int g_cnt[NSEG];
__device__ int g_seg_start[NSEG + 1];
__device__ int g_cursor[NSEG];
__device__ int g_esrc[N_EDGES];

// ---------------- PTX helpers ----------------
__device__ __forceinline__ uint32_t smem_to_u32(const void* p) {
    uint32_t a;
    asm("{ .reg .u64 t; cvta.to.shared.u64 t, %1; cvt.u32.u64 %0, t; }" : "=r"(a) : "l"(p));
    return a;
}
#define CP_ASYNC16(dst, src) \
    asm volatile("cp.async.cg.shared.global [%0], [%1], 16;" :: "r"(dst), "l"(src) : "memory")
#define CP_ASYNC_COMMIT() asm volatile("cp.async.commit_group;" ::: "memory")
#define CP_ASYNC_WAIT(n)  asm volatile("cp.async.wait_group %0;" :: "n"(n) : "memory")
__device__ __forceinline__ void ldsm4(uint32_t (&r)[4], uint32_t addr) {
    asm volatile("ldmatrix.sync.aligned.m8n8.x4.shared.b16 {%0,%1,%2,%3}, [%4];"
                 : "=r"(r[0]), "=r"(r[1]), "=r"(r[2]), "=r"(r[3]) : "r"(addr));
}
#define IMMA_DEF(name, at, bt) \
__device__ __forceinline__ void name(int (&d)[4], const uint32_t (&a)[4], uint32_t b0, uint32_t b1) { \
    asm volatile("mma.sync.aligned.m16n8k32.row.col.s32." at "." bt ".s32 " \
        "{%0,%1,%2,%3},{%4,%5,%6,%7},{%8,%9},{%0,%1,%2,%3};" \
        : "+r"(d[0]), "+r"(d[1]), "+r"(d[2]), "+r"(d[3]) \
        : "r"(a[0]), "r"(a[1]), "r"(a[2]), "r"(a[3]), "r"(b0), "r"(b1)); \
}
IMMA_DEF(imma_ss, "s8", "s8")
IMMA_DEF(imma_su, "s8", "u8")
IMMA_DEF(imma_us, "u8", "s8")
IMMA_DEF(imma_uu, "u8", "u8")
#define SWZ(off) ((off) ^ (((off) >> 3) & 0x70))

__device__ __forceinline__ void quant15(float v, float s, signed char& q1, unsigned char& q2) {
    int t = (int)rintf(v * s);
    t = max(-32512, min(32512, t));
    int h = ((t + 32768) >> 8) - 128;       // floor(t/256)
    q1 = (signed char)h;
    q2 = (unsigned char)(t - (h << 8));     // in [0,255]
}
__device__ __forceinline__ void amax_atomic(float* p, float m) {
    atomicMax((int*)p, __float_as_int(m));  // valid: m >= 0
}

// ---------------- edge preprocessing ----------------
__global__ void zero_cnt_kernel() {
    int i = blockIdx.x * blockDim.x + threadIdx.x;
    if (i < NSEG) g_cnt[i] = 0;
}
__global__ void count_kernel(const int* __restrict__ ei, const int* __restrict__ et) {
    int e = blockIdx.x * blockDim.x + threadIdx.x;
    if (e >= N_EDGES) return;
    atomicAdd(&g_cnt[ei[N_EDGES + e] * N_REL + et[e]], 1);
}
__global__ void scan_kernel() {
    __shared__ int part[1024];
    const int CHK = (NSEG + 1023) / 1024;
    int tid = threadIdx.x, degs[CHK], mysum = 0;
#pragma unroll
    for (int i = 0; i < CHK; i++) {
        int d = tid * CHK + i;
        int dg = (d < NSEG) ? g_cnt[d] : 0;
        degs[i] = dg; mysum += dg;
    }
    part[tid] = mysum;
    __syncthreads();
    if (tid == 0) {
        int run = 0;
        for (int t = 0; t < 1024; t++) { int v = part[t]; part[t] = run; run += v; }
        g_seg_start[NSEG] = run;
    }
    __syncthreads();
    int off = part[tid];
#pragma unroll
    for (int i = 0; i < CHK; i++) {
        int d = tid * CHK + i;
        if (d < NSEG) { g_seg_start[d] = off; g_cursor[d] = off; off += degs[i]; }
    }
}
__global__ void fill_kernel(const int* __restrict__ ei, const int* __restrict__ et) {
    int e = blockIdx.x * blockDim.x + threadIdx.x;
    if (e >= N_EDGES) return;
    int seg = ei[N_EDGES + e] * N_REL + et[e];
    g_esrc[atomicAdd(&g_cursor[seg], 1)] = ei[e];
}

// ---------------- xfill: root slot fp32 + row amax ----------------
__global__ void xfill_kernel(const float* __restrict__ x, const float* __restrict__ gene) {
    __shared__ float red[256];
    int node = blockIdx.x, tid = threadIdx.x;
    const float* row = (node < N_DRUGS) ? (x + (size_t)node * IN_DIM)
                                        : (gene + (size_t)(node - N_DRUGS) * IN_DIM);
    float tmax = 0.f;
    size_t base = (size_t)node * KC1 + 4 * KP1;
    for (int k = tid; k < IN_DIM; k += 256) {
        float v = row[k];
        g_Xf[base + k] = v;
        tmax = fmaxf(tmax, fabsf(v));
    }
    red[tid] = tmax; __syncthreads();
    for (int o = 128; o > 0; o >>= 1) {
        if (tid < o) red[tid] = fmaxf(red[tid], red[tid + o]);
        __syncthreads();
    }
    if (tid == 0) amax_atomic(&g_amaxX[node], red[0]);
}

// ---------------- segment mean -> fp32 slot + amax ----------------
template <int CH>
__global__ void agg_seg_kernel(const float* __restrict__ s0, const float* __restrict__ s1,
                               int splitRow, int D, int Kpad, int KC,
                               float* __restrict__ catF, float* __restrict__ amaxOut) {
    __shared__ float red[256];
    int seg = blockIdx.x;
    int s = g_seg_start[seg], e = g_seg_start[seg + 1];
    if (s == e) return;
    int tid = threadIdx.x;
    float acc[CH];
#pragma unroll
    for (int j = 0; j < CH; j++) acc[j] = 0.f;
    for (int p = s; p < e; p++) {
        int sn = g_esrc[p];
        const float* row = (sn < splitRow) ? (s0 + (size_t)sn * D)
                                           : (s1 + (size_t)(sn - splitRow) * D);
#pragma unroll
        for (int j = 0; j < CH; j++) {
            int o = tid + j * 256;
            if (o < D) acc[j] += row[o];
        }
    }
    float inv = 1.0f / (float)(e - s);
    int node = seg >> 2, rel = seg & 3;
    size_t base = (size_t)node * KC + (size_t)rel * Kpad;
    float tmax = 0.f;
#pragma unroll
    for (int j = 0; j < CH; j++) {
        int o = tid + j * 256;
        if (o < D) {
            float v = acc[j] * inv;
            catF[base + o] = v;
            tmax = fmaxf(tmax, fabsf(v));
        }
    }
    red[tid] = tmax; __syncthreads();
    for (int o = 128; o > 0; o >>= 1) {
        if (tid < o) red[tid] = fmaxf(red[tid], red[tid + o]);
        __syncthreads();
    }
    if (tid == 0) amax_atomic(&amaxOut[node], red[0]);
}

// ---------------- quantize rows ----------------
__global__ void quantize_kernel(const float* __restrict__ f, const float* __restrict__ amax,
                                signed char* __restrict__ q1, unsigned char* __restrict__ q2, int KC) {
    int r = blockIdx.y;
    int k = blockIdx.x * 256 + threadIdx.x;
    if (k >= KC) return;
    float am = amax[r];
    float s = (am > 0.f) ? (QMAXF / am) : 0.f;
    size_t i = (size_t)r * KC + k;
    quant15(f[i], s, q1[i], q2[i]);
}

// ---------------- weight prep: column amax + transpose-quantize ----------------
__global__ void colmax_kernel(const float* __restrict__ Wrel, const float* __restrict__ Wroot,
                              int K, int N, int nz, float* __restrict__ cmax) {
    int n = blockIdx.x * blockDim.x + threadIdx.x;
    if (n >= N) return;
    int z = blockIdx.y >> 3, slice = blockIdx.y & 7;
    const float* W = (z == nz - 1) ? Wroot : (Wrel + (size_t)z * K * N);
    float m = 0.f;
    for (int k = slice; k < K; k += 8) m = fmaxf(m, fabsf(W[(size_t)k * N + n]));
    amax_atomic(&cmax[n], m);
}
__global__ void transpose_quant_kernel(const float* __restrict__ Wrel, const float* __restrict__ Wroot,
                                       signed char* __restrict__ Tq1, unsigned char* __restrict__ Tq2,
                                       const float* __restrict__ cmax,
                                       int K, int N, int Kpad, int KC, int nz) {
    __shared__ float t[32][33];
    int z = blockIdx.z;
    const float* W = (z == nz - 1) ? Wroot : (Wrel + (size_t)z * K * N);
    int k0 = blockIdx.x * 32, n0 = blockIdx.y * 32;
    int tx = threadIdx.x, ty = threadIdx.y;
#pragma unroll
    for (int i = 0; i < 4; i++) {
        int k = k0 + ty + i * 8, n = n0 + tx;
        t[ty + i * 8][tx] = (k < K && n < N) ? W[(size_t)k * N + n] : 0.f;
    }
    __syncthreads();
#pragma unroll
    for (int i = 0; i < 4; i++) {
        int n = n0 + ty + i * 8, kk = k0 + tx;
        if (n < N && kk < K) {
            float am = cmax[n];
            float s = (am > 0.f) ? (QMAXF / am) : 0.f;
            size_t o = (size_t)n * KC + (size_t)z * Kpad + kk;
            quant15(t[tx][ty + i * 8], s, Tq1[o], Tq2[o]);
        }
    }
}

// ---------------- int8 2-digit GEMM: CTA 128x64, BK=128, 16 warps (32x16) ----------------
#define AT_B  16384
#define BT_B  8192
#define STAGE_B (2 * AT_B + 2 * BT_B)   // 48 KB
#define GEMM_SMEM (3 * STAGE_B)         // 144 KB
#define GTHREADS 512

__global__ void __launch_bounds__(GTHREADS, 1)
gemm_i8_kernel(const signed char* __restrict__ Aq1, const unsigned char* __restrict__ Aq2,
               const signed char* __restrict__ Bq1, const unsigned char* __restrict__ Bq2,
               const float* __restrict__ amaxA, const float* __restrict__ amaxB,
               int KC, int Nout, const float* __restrict__ bias,
               float* __restrict__ outF,
               float* __restrict__ catF, int strideO, int colOff,
               float* __restrict__ amaxOut) {
    extern __shared__ char dsm[];
    const uint32_t sbase = smem_to_u32(dsm);
    const int tid = threadIdx.x, lane = tid & 31, wid = tid >> 5;
    const int m_off = (wid >> 2) * 32, n_off = (wid & 3) * 16;
    const int m0 = blockIdx.y * 128, n0 = blockIdx.x * 64;

    const int arow = lane & 15;
    const uint32_t xorv = (uint32_t)(arow & 7) << 4;
    uint32_t colp[4];
#pragma unroll
    for (int ks = 0; ks < 4; ks++)
        colp[ks] = ((uint32_t)(ks * 32 + ((lane >> 4) * 16))) ^ xorv;
    uint32_t rowA[2];
#pragma unroll
    for (int mi = 0; mi < 2; mi++) rowA[mi] = (uint32_t)(m_off + mi * 16 + arow) * 128u;
    uint32_t rowB = (uint32_t)(n_off + arow) * 128u;

    int hh[2][2][4], xx[2][2][4], ll[2][2][4];
#pragma unroll
    for (int mi = 0; mi < 2; mi++)
#pragma unroll
        for (int nt = 0; nt < 2; nt++)
#pragma unroll
            for (int q = 0; q < 4; q++) { hh[mi][nt][q] = 0; xx[mi][nt][q] = 0; ll[mi][nt][q] = 0; }

    const int chunks = KC >> 7;

    auto load_stage = [&](int slot, int c) {
        const int k0 = c << 7;
        const uint32_t base = sbase + (uint32_t)slot * STAGE_B;
#pragma unroll
        for (int i = 0; i < 6; i++) {
            int idx = tid + i * GTHREADS;
            const char* g; uint32_t d;
            if (idx < 2048) {
                int t = idx >> 10, r = (idx >> 3) & 127, j = idx & 7;
                g = (t ? (const char*)Aq2 : (const char*)Aq1) + (size_t)(m0 + r) * KC + k0 + j * 16;
                d = base + (uint32_t)t * AT_B + SWZ((uint32_t)(r * 128 + j * 16));
            } else {
                int i2 = idx - 2048;
                int t = i2 >> 9, r = (i2 >> 3) & 63, j = i2 & 7;
                g = (t ? (const char*)Bq2 : (const char*)Bq1) + (size_t)(n0 + r) * KC + k0 + j * 16;
                d = base + 2 * AT_B + (uint32_t)t * BT_B + SWZ((uint32_t)(r * 128 + j * 16));
            }
            CP_ASYNC16(d, (const void*)g);
        }
        CP_ASYNC_COMMIT();
    };

    load_stage(0, 0);
    if (chunks > 1) load_stage(1, 1);

    for (int c = 0; c < chunks; c++) {
        if (c + 1 < chunks) CP_ASYNC_WAIT(1);
        else                CP_ASYNC_WAIT(0);
        __syncthreads();
        if (c + 2 < chunks) load_stage((c + 2) % 3, c + 2);

        const uint32_t sb = sbase + (uint32_t)(c % 3) * STAGE_B;
#pragma unroll
        for (int ks = 0; ks < 4; ks++) {
            uint32_t a1[2][4], a2[2][4], t1[4], t2[4];
#pragma unroll
            for (int mi = 0; mi < 2; mi++) {
                ldsm4(a1[mi], sb + rowA[mi] + colp[ks]);
                ldsm4(a2[mi], sb + AT_B + rowA[mi] + colp[ks]);
            }
            ldsm4(t1, sb + 2 * AT_B + rowB + colp[ks]);
            ldsm4(t2, sb + 2 * AT_B + BT_B + rowB + colp[ks]);
#pragma unroll
            for (int mi = 0; mi < 2; mi++)
#pragma unroll
                for (int nt = 0; nt < 2; nt++) {
                    uint32_t b10 = nt ? t1[1] : t1[0], b11 = nt ? t1[3] : t1[2];
                    uint32_t b20 = nt ? t2[1] : t2[0], b21 = nt ? t2[3] : t2[2];
                    imma_ss(hh[mi][nt], a1[mi], b10, b11);
                    imma_su(xx[mi][nt], a1[mi], b20, b21);
                    imma_us(xx[mi][nt], a2[mi], b10, b11);
                    imma_uu(ll[mi][nt], a2[mi], b20, b21);
                }
        }
    }

    __syncthreads();
    float* sC = (float*)dsm;                 // 128 x 68
#pragma unroll
    for (int mi = 0; mi < 2; mi++)
#pragma unroll
        for (int nt = 0; nt < 2; nt++) {
            int r0 = m_off + mi * 16 + (lane >> 2);
            int c0 = n_off + nt * 8 + (lane & 3) * 2;
#pragma unroll
            for (int q = 0; q < 4; q++) {
                long long v = 65536LL * (long long)hh[mi][nt][q]
                            + 256LL * (long long)xx[mi][nt][q]
                            + (long long)ll[mi][nt][q];
                int rr = r0 + (q >> 1) * 8, ccx = c0 + (q & 1);
                sC[rr * 68 + ccx] = (float)v;
            }
        }
    __syncthreads();
    const float invq = 1.f / (QMAXF * QMAXF);
#pragma unroll
    for (int i = 0; i < 16; i++) {
        int idx = tid + i * GTHREADS;
        int r = idx >> 6, cc = idx & 63;
        int gm = m0 + r, gn = n0 + cc;
        if (gm < NNODES && gn < Nout) {
            float v = amaxA[gm] * amaxB[gn] * invq * sC[r * 68 + cc] + bias[gn];
            v = fmaxf(v, 0.f);
            if (outF) outF[(size_t)gm * Nout + gn] = v;
            if (catF) catF[(size_t)gm * strideO + colOff + gn] = v;
            if (amaxOut) amax_atomic(&amaxOut[gm], v);
        }
    }
}

// ---------------- head ----------------
__global__ void logits_kernel(const float* __restrict__ emb, const float* __restrict__ w,
                              const float* __restrict__ b, float* __restrict__ out) {
    int gtid = blockIdx.x * blockDim.x + threadIdx.x;
    int node = gtid >> 5, lane = gtid & 31;
    if (node >= NNODES) return;
    const float* e = emb + (size_t)node * DIM3;
    float s0 = 0.f, s1 = 0.f;
    for (int k = lane; k < DIM3; k += 32) {
        float v = e[k];
        s0 = fmaf(v, w[2 * k + 0], s0);
        s1 = fmaf(v, w[2 * k + 1], s1);
    }
#pragma unroll
    for (int o = 16; o; o >>= 1) {
        s0 += __shfl_down_sync(0xffffffffu, s0, o);
        s1 += __shfl_down_sync(0xffffffffu, s1, o);
    }
    if (lane == 0) {
        s0 += b[0]; s1 += b[1];
        float m = fmaxf(s0, s1);
        float l = m + logf(expf(s0 - m) + expf(s1 - m));
        out[2 * node + 0] = s0 - l;
        out[2 * node + 1] = s1 - l;
    }
}

// ---------------- launch ----------------
extern "C" void kernel_launch(void* const* d_in, const int* in_sizes, int n_in,
                              void* d_out, int out_size) {
    const float* x      = (const float*)d_in[0];
    const float* gene   = (const float*)d_in[1];
    const float* w_rel1 = (const float*)d_in[2];
    const float* root1  = (const float*)d_in[3];
    const float* b1     = (const float*)d_in[4];
    const float* w_rel2 = (const float*)d_in[5];
    const float* root2  = (const float*)d_in[6];
    const float* b2     = (const float*)d_in[7];
    const float* lin1_w = (const float*)d_in[8];
    const float* lin1_b = (const float*)d_in[9];
    const float* lin2_w = (const float*)d_in[10];
    const float* lin2_b = (const float*)d_in[11];
    const int* ei = (const int*)d_in[12];
    const int* et = (const int*)d_in[13];
    float* out = (float*)d_out;

    float *Xf, *A1, *A1f, *A2f, *amX, *amA1, *amA2, *cm1, *cm2, *cm3;
    signed char *Xq1, *W1q1, *A1q1, *W2q1, *A2q1, *W3q1;
    unsigned char *Xq2, *W1q2, *A1q2, *W2q2, *A2q2, *W3q2;
    cudaGetSymbolAddress((void**)&Xf, g_Xf);
    cudaGetSymbolAddress((void**)&Xq1, g_Xq1);   cudaGetSymbolAddress((void**)&Xq2, g_Xq2);
    cudaGetSymbolAddress((void**)&W1q1, g_W1q1); cudaGetSymbolAddress((void**)&W1q2, g_W1q2);
    cudaGetSymbolAddress((void**)&A1, g_A1);     cudaGetSymbolAddress((void**)&A1f, g_A1f);
    cudaGetSymbolAddress((void**)&A1q1, g_A1q1); cudaGetSymbolAddress((void**)&A1q2, g_A1q2);
    cudaGetSymbolAddress((void**)&W2q1, g_W2q1); cudaGetSymbolAddress((void**)&W2q2, g_W2q2);
    cudaGetSymbolAddress((void**)&A2f, g_A2f);
    cudaGetSymbolAddress((void**)&A2q1, g_A2q1); cudaGetSymbolAddress((void**)&A2q2, g_A2q2);
    cudaGetSymbolAddress((void**)&W3q1, g_W3q1); cudaGetSymbolAddress((void**)&W3q2, g_W3q2);
    cudaGetSymbolAddress((void**)&amX, g_amaxX);
    cudaGetSymbolAddress((void**)&amA1, g_amaxA1);
    cudaGetSymbolAddress((void**)&amA2, g_amaxA2);
    cudaGetSymbolAddress((void**)&cm1, g_cmax1);
    cudaGetSymbolAddress((void**)&cm2, g_cmax2);
    cudaGetSymbolAddress((void**)&cm3, g_cmax3);

    cudaFuncSetAttribute(gemm_i8_kernel, cudaFuncAttributeMaxDynamicSharedMemorySize, GEMM_SMEM);
    dim3 tb32(32, 8);

    // edge prep
    zero_cnt_kernel<<<(NSEG + 255) / 256, 256>>>();
    count_kernel<<<(N_EDGES + 255) / 256, 256>>>(ei, et);
    scan_kernel<<<1, 1024>>>();
    fill_kernel<<<(N_EDGES + 255) / 256, 256>>>(ei, et);

    // weights: cmax + transpose-quantize
    colmax_kernel<<<dim3((DIM1 + 255) / 256, 40), 256>>>(w_rel1, root1, IN_DIM, DIM1, 5, cm1);
    colmax_kernel<<<dim3((DIM2 + 255) / 256, 40), 256>>>(w_rel2, root2, DIM1, DIM2, 5, cm2);
    colmax_kernel<<<dim3((DIM3 + 255) / 256, 8), 256>>>(nullptr, lin1_w, DIM2, DIM3, 1, cm3);
    transpose_quant_kernel<<<dim3(KP1 / 32, (DIM1 + 31) / 32, 5), tb32>>>(w_rel1, root1, W1q1, W1q2, cm1, IN_DIM, DIM1, KP1, KC1, 5);
    transpose_quant_kernel<<<dim3(KP2 / 32, (DIM2 + 31) / 32, 5), tb32>>>(w_rel2, root2, W2q1, W2q2, cm2, DIM1, DIM2, KP2, KC2, 5);
    transpose_quant_kernel<<<dim3(KP3 / 32, (DIM3 + 31) / 32, 1), tb32>>>(nullptr, lin1_w, W3q1, W3q2, cm3, DIM2, DIM3, KP3, KP3, 1);

    // layer-1 inputs: root fill + per-relation means, then quantize
    xfill_kernel<<<NNODES, 256>>>(x, gene);
    agg_seg_kernel<7><<<NSEG, 256>>>(x, gene, N_DRUGS, IN_DIM, KP1, KC1, Xf, amX);
    quantize_kernel<<<dim3((KC1 + 255) / 256, MPAD), 256>>>(Xf, amX, Xq1, Xq2, KC1);

    // layer-1 GEMM
    gemm_i8_kernel<<<dim3(NP1 / 64, MPAD / 128), GTHREADS, GEMM_SMEM>>>(
        Xq1, Xq2, W1q1, W1q2, amX, cm1, KC1, DIM1, b1,
        A1, A1f, KC2, 4 * KP2, amA1);

    // layer-2 inputs + quantize
    agg_seg_kernel<6><<<NSEG, 256>>>(A1, A1, NNODES, DIM1, KP2, KC2, A1f, amA1);
    quantize_kernel<<<dim3((KC2 + 255) / 256, MPAD), 256>>>(A1f, amA1, A1q1, A1q2, KC2);

    // layer-2 GEMM
    gemm_i8_kernel<<<dim3(NP2 / 64, MPAD / 128), GTHREADS, GEMM_SMEM>>>(
        A1q1, A1q2, W2q1, W2q2, amA1, cm2, KC2, DIM2, b2,
        nullptr, A2f, KP3, 0, amA2);
    quantize_kernel<<<dim3((KP3 + 255) / 256, MPAD), 256>>>(A2f, amA2, A2q1, A2q2, KP3);

    // lin1 -> emb (in output buffer)
    float* emb = out + 2 * NNODES;
    gemm_i8_kernel<<<dim3(NP3 / 64, MPAD / 128), GTHREADS, GEMM_SMEM>>>(
        A2q1, A2q2, W3q1, W3q2, amA2, cm3, KP3, DIM3, lin1_b,
        emb, nullptr, 0, 0, nullptr);

    // head
    logits_kernel<<<(NNODES * 32 + 255) / 256, 256>>>(emb, lin2_w, lin2_b, out);
}

// round 12
// speedup vs baseline: 3.7081x; 3.7081x over previous
#include <cuda_runtime.h>
#include <cuda_bf16.h>
#include <cstdint>
#include <math.h>

// ---------------- problem constants ----------------
#define N_DRUGS   4000
#define N_GENES   4264
#define NNODES    8264
#define IN_DIM    1613
#define DIM1      1340
#define DIM2      920
#define DIM3      740
#define N_REL     4
#define N_EDGES   100000
#define NSEG      (NNODES * N_REL)     // 33056

#define MPAD      8320                 // 65 * 128
#define KP1       1664                 // pad(1613, 64)
#define KP2       1344                 // pad(1340, 64)
#define KP3       960                  // pad(920, 64)
#define KC1       (5 * KP1)            // 8320
#define KC2       (5 * KP2)            // 6720
#define NP1       1408                 // 11 * 128
#define NP2       960                  // 15 * 64   (was 1024: -6% work)
#define NP3       768                  // 6 * 128

// ---------------- device scratch ----------------
__device__ __nv_bfloat16 g_Xcat_hi[(size_t)MPAD * KC1];
__device__ __nv_bfloat16 g_Xcat_lo[(size_t)MPAD * KC1];
__device__ __nv_bfloat16 g_W1hi[(size_t)NP1 * KC1];
__device__ __nv_bfloat16 g_W1lo[(size_t)NP1 * KC1];
__device__ float         g_A1[(size_t)NNODES * DIM1];
__device__ __nv_bfloat16 g_A1cat_hi[(size_t)MPAD * KC2];
__device__ __nv_bfloat16 g_A1cat_lo[(size_t)MPAD * KC2];
__device__ __nv_bfloat16 g_W2hi[(size_t)NP2 * KC2];
__device__ __nv_bfloat16 g_W2lo[(size_t)NP2 * KC2];
__device__ __nv_bfloat16 g_A2hi[(size_t)MPAD * KP3];
__device__ __nv_bfloat16 g_A2lo[(size_t)MPAD * KP3];
__device__ __nv_bfloat16 g_W3hi[(size_t)NP3 * KP3];
__device__ __nv_bfloat16 g_W3lo[(size_t)NP3 * KP3];
__device__ int g_cnt[NSEG];
__device__ int g_seg_start[NSEG + 1];
__device__ int g_cursor[NSEG];
__device__ int g_esrc[N_EDGES];

// ---------------- PTX helpers (plain sm_80+ instructions only) ----------------
__device__ __forceinline__ uint32_t smem_to_u32(const void* p) {
    uint32_t a;
    asm("{ .reg .u64 t; cvta.to.shared.u64 t, %1; cvt.u32.u64 %0, t; }" : "=r"(a) : "l"(p));
    return a;
}
#define CP_ASYNC16(dst, src) \
    asm volatile("cp.async.cg.shared.global [%0], [%1], 16;" :: "r"(dst), "l"(src) : "memory")
#define CP_ASYNC_COMMIT() asm volatile("cp.async.commit_group;" ::: "memory")
#define CP_ASYNC_WAIT(n)  asm volatile("cp.async.wait_group %0;" :: "n"(n) : "memory")

__device__ __forceinline__ void ldsm4(uint32_t (&r)[4], uint32_t addr) {
    asm volatile("ldmatrix.sync.aligned.m8n8.x4.shared.b16 {%0,%1,%2,%3}, [%4];"
                 : "=r"(r[0]), "=r"(r[1]), "=r"(r[2]), "=r"(r[3]) : "r"(addr));
}
__device__ __forceinline__ void mma16816(float (&d)[4], const uint32_t (&a)[4],
                                         uint32_t b0, uint32_t b1) {
    asm volatile(
        "mma.sync.aligned.m16n8k16.row.col.f32.bf16.bf16.f32 "
        "{%0,%1,%2,%3}, {%4,%5,%6,%7}, {%8,%9}, {%0,%1,%2,%3};"
        : "+f"(d[0]), "+f"(d[1]), "+f"(d[2]), "+f"(d[3])
        : "r"(a[0]), "r"(a[1]), "r"(a[2]), "r"(a[3]), "r"(b0), "r"(b1));
}
#define SWZ(off) ((off) ^ (((off) >> 3) & 0x70))

// ---------------- prep: x -> Xcat root slot (bf16 hi/lo) ----------------
__global__ void xfill_kernel(const float* __restrict__ x, const float* __restrict__ gene)
{
    size_t i = (size_t)blockIdx.x * blockDim.x + threadIdx.x;
    const size_t TOT = (size_t)NNODES * IN_DIM;
    if (i >= TOT) return;
    int node = (int)(i / IN_DIM);
    int k = (int)(i % IN_DIM);
    float v = (node < N_DRUGS) ? x[(size_t)node * IN_DIM + k]
                               : gene[(size_t)(node - N_DRUGS) * IN_DIM + k];
    __nv_bfloat16 hi = __float2bfloat16(v);
    size_t o = (size_t)node * KC1 + 4 * KP1 + k;
    g_Xcat_hi[o] = hi;
    g_Xcat_lo[o] = __float2bfloat16(v - __bfloat162float(hi));
}

// transpose W[K][N] (z slabs) -> Wcat[n][z*Kpad + k] hi/lo, zero-padded
__global__ void transpose_split_kernel(const float* __restrict__ Wrel,
                                       const float* __restrict__ Wroot,
                                       __nv_bfloat16* __restrict__ Thi,
                                       __nv_bfloat16* __restrict__ Tlo,
                                       int K, int N, int Kpad, int KC, int Npad)
{
    __shared__ float t[32][33];
    int z = blockIdx.z;
    const float* W = (Wrel != nullptr && z < N_REL) ? (Wrel + (size_t)z * K * N) : Wroot;
    int k0 = blockIdx.x * 32;
    int n0 = blockIdx.y * 32;
    int tx = threadIdx.x, ty = threadIdx.y;
#pragma unroll
    for (int i = 0; i < 4; i++) {
        int k = k0 + ty + i * 8;
        int n = n0 + tx;
        t[ty + i * 8][tx] = (k < K && n < N) ? W[(size_t)k * N + n] : 0.f;
    }
    __syncthreads();
#pragma unroll
    for (int i = 0; i < 4; i++) {
        int n = n0 + ty + i * 8;
        int kk = k0 + tx;
        float v = t[tx][ty + i * 8];
        __nv_bfloat16 hi = __float2bfloat16(v);
        size_t o = (size_t)n * KC + (size_t)z * Kpad + kk;
        Thi[o] = hi;
        Tlo[o] = __float2bfloat16(v - __bfloat162float(hi));
    }
}

// ---------------- edge preprocessing ----------------
__global__ void zero_cnt_kernel()
{
    int i = blockIdx.x * blockDim.x + threadIdx.x;
    if (i < NSEG) g_cnt[i] = 0;
}
__global__ void count_kernel(const int* __restrict__ ei, const int* __restrict__ et)
{
    int e = blockIdx.x * blockDim.x + threadIdx.x;
    if (e >= N_EDGES) return;
    atomicAdd(&g_cnt[ei[N_EDGES + e] * N_REL + et[e]], 1);
}
__global__ void scan_kernel()
{
    __shared__ int part[1024];
    const int CHK = (NSEG + 1023) / 1024;
    int tid = threadIdx.x;
    int degs[CHK];
    int mysum = 0;
#pragma unroll
    for (int i = 0; i < CHK; i++) {
        int d = tid * CHK + i;
        int dg = (d < NSEG) ? g_cnt[d] : 0;
        degs[i] = dg;
        mysum += dg;
    }
    part[tid] = mysum;
    __syncthreads();
    if (tid == 0) {
        int run = 0;
        for (int t = 0; t < 1024; t++) { int v = part[t]; part[t] = run; run += v; }
        g_seg_start[NSEG] = run;
    }
    __syncthreads();
    int off = part[tid];
#pragma unroll
    for (int i = 0; i < CHK; i++) {
        int d = tid * CHK + i;
        if (d < NSEG) { g_seg_start[d] = off; g_cursor[d] = off; off += degs[i]; }
    }
}
__global__ void fill_kernel(const int* __restrict__ ei, const int* __restrict__ et)
{
    int e = blockIdx.x * blockDim.x + threadIdx.x;
    if (e >= N_EDGES) return;
    int seg = ei[N_EDGES + e] * N_REL + et[e];
    g_esrc[atomicAdd(&g_cursor[seg], 1)] = ei[e];
}

// ---------------- segment-mean aggregation, emits bf16 hi/lo ----------------
template <int CH>
__global__ void agg_seg_kernel(const float* __restrict__ src0, const float* __restrict__ src1,
                               int splitRow, int D, int Kpad, int KC,
                               __nv_bfloat16* __restrict__ outHi, __nv_bfloat16* __restrict__ outLo)
{
    int seg = blockIdx.x;
    int s = g_seg_start[seg];
    int e = g_seg_start[seg + 1];
    if (s == e) return;
    int tid = threadIdx.x;
    float acc[CH];
#pragma unroll
    for (int j = 0; j < CH; j++) acc[j] = 0.f;
    for (int p = s; p < e; p++) {
        int sn = g_esrc[p];
        const float* row = (sn < splitRow) ? (src0 + (size_t)sn * D)
                                           : (src1 + (size_t)(sn - splitRow) * D);
#pragma unroll
        for (int j = 0; j < CH; j++) {
            int o = tid + j * 256;
            if (o < D) acc[j] += row[o];
        }
    }
    float inv = 1.0f / (float)(e - s);
    int node = seg >> 2, rel = seg & 3;
    size_t base = (size_t)node * KC + (size_t)rel * Kpad;
#pragma unroll
    for (int j = 0; j < CH; j++) {
        int o = tid + j * 256;
        if (o < D) {
            float v = acc[j] * inv;
            __nv_bfloat16 hi = __float2bfloat16(v);
            outHi[base + o] = hi;
            outLo[base + o] = __float2bfloat16(v - __bfloat162float(hi));
        }
    }
}

// ---------------- mma.sync bf16-split GEMM, templated on N tile ----------------
// C[m][n] = relu( sum_k A[m][k]*W[n][k] + bias[n] ),  A=Ahi+Alo, W=Whi+Wlo (3-term)
// CTA tile 128 x NBLK, BK=64, 3-stage cp.async, 16 warps (4m x 4n).
#define TILE_B  (128 * 128)          // A tile bytes
#define GTHREADS 512

template <int NBLK>
__global__ void __launch_bounds__(GTHREADS, 1)
gemm_mma_kernel(const __nv_bfloat16* __restrict__ Ahi, const __nv_bfloat16* __restrict__ Alo,
                const __nv_bfloat16* __restrict__ Bhi, const __nv_bfloat16* __restrict__ Blo,
                int KC, int Nout, const float* __restrict__ bias,
                float* __restrict__ outF,
                __nv_bfloat16* __restrict__ outHi, __nv_bfloat16* __restrict__ outLo,
                int strideO, int colOff)
{
    constexpr int BT_B = NBLK * 128;             // B tile bytes
    constexpr int STAGE_B = 2 * TILE_B + 2 * BT_B;
    constexpr int WN = NBLK / 4;                 // warp n-tile
    constexpr int NR = WN / 16;                  // ldsm rows of B per warp
    constexpr int NT = WN / 8;                   // 8-wide mma n-tiles per warp
    constexpr int LOADS = (2048 + 16 * NBLK) / GTHREADS;  // cp.async per thread

    extern __shared__ char dsm[];
    const uint32_t sbase = smem_to_u32(dsm);
    const int tid = threadIdx.x;
    const int lane = tid & 31;
    const int wid = tid >> 5;                 // 0..15
    const int m_off = (wid >> 2) * 32;        // 4 m-groups of 32
    const int n_off = (wid & 3) * WN;         // 4 n-groups of WN
    const int m0 = blockIdx.y * 128;
    const int n0 = blockIdx.x * NBLK;

    const int arow = lane & 15;
    const uint32_t xorv = (uint32_t)(arow & 7) << 4;
    uint32_t colp[4];
#pragma unroll
    for (int ks = 0; ks < 4; ks++)
        colp[ks] = ((uint32_t)(ks * 32 + ((lane >> 4) * 16))) ^ xorv;
    uint32_t rowA[2], rowB[NR];
#pragma unroll
    for (int mi = 0; mi < 2; mi++) rowA[mi] = (uint32_t)(m_off + mi * 16 + arow) * 128u;
#pragma unroll
    for (int nj = 0; nj < NR; nj++) rowB[nj] = (uint32_t)(n_off + nj * 16 + arow) * 128u;

    float acc[2][NT][4];
#pragma unroll
    for (int mi = 0; mi < 2; mi++)
#pragma unroll
        for (int nt = 0; nt < NT; nt++)
#pragma unroll
            for (int q = 0; q < 4; q++) acc[mi][nt][q] = 0.f;

    const int chunks = KC >> 6;

    auto load_stage = [&](int slot, int c) {
        const int k0 = c << 6;
        const uint32_t base = sbase + (uint32_t)slot * STAGE_B;
#pragma unroll
        for (int i = 0; i < LOADS; i++) {
            int idx = tid + i * GTHREADS;
            const __nv_bfloat16* g;
            uint32_t d;
            if (idx < 2048) {
                int t = idx >> 10;              // 0: Ahi, 1: Alo
                int r = (idx >> 3) & 127, j = idx & 7;
                g = (t ? Alo : Ahi) + (size_t)(m0 + r) * KC + k0 + j * 8;
                d = base + (uint32_t)t * TILE_B + SWZ((uint32_t)(r * 128 + j * 16));
            } else {
                int i2 = idx - 2048;
                int t = i2 / (8 * NBLK);        // 0: Bhi, 1: Blo
                int r = (i2 >> 3) % NBLK, j = i2 & 7;
                g = (t ? Blo : Bhi) + (size_t)(n0 + r) * KC + k0 + j * 8;
                d = base + 2 * TILE_B + (uint32_t)t * BT_B + SWZ((uint32_t)(r * 128 + j * 16));
            }
            CP_ASYNC16(d, (const void*)g);
        }
        CP_ASYNC_COMMIT();
    };

    load_stage(0, 0);
    if (chunks > 1) load_stage(1, 1);

    for (int c = 0; c < chunks; c++) {
        if (c + 1 < chunks) CP_ASYNC_WAIT(1);
        else                CP_ASYNC_WAIT(0);
        __syncthreads();
        if (c + 2 < chunks) load_stage((c + 2) % 3, c + 2);

        const uint32_t sb = sbase + (uint32_t)(c % 3) * STAGE_B;
#pragma unroll
        for (int ks = 0; ks < 4; ks++) {
            uint32_t ah[2][4], al[2][4];
            uint32_t bh[NT][2], bl[NT][2];
#pragma unroll
            for (int mi = 0; mi < 2; mi++) {
                ldsm4(ah[mi], sb + rowA[mi] + colp[ks]);
                ldsm4(al[mi], sb + TILE_B + rowA[mi] + colp[ks]);
            }
#pragma unroll
            for (int nj = 0; nj < NR; nj++) {
                uint32_t t4[4];
                ldsm4(t4, sb + 2 * TILE_B + rowB[nj] + colp[ks]);
                bh[2 * nj][0] = t4[0]; bh[2 * nj][1] = t4[2];
                bh[2 * nj + 1][0] = t4[1]; bh[2 * nj + 1][1] = t4[3];
                ldsm4(t4, sb + 2 * TILE_B + BT_B + rowB[nj] + colp[ks]);
                bl[2 * nj][0] = t4[0]; bl[2 * nj][1] = t4[2];
                bl[2 * nj + 1][0] = t4[1]; bl[2 * nj + 1][1] = t4[3];
            }
#pragma unroll
            for (int mi = 0; mi < 2; mi++)
#pragma unroll
                for (int nt = 0; nt < NT; nt++) {
                    mma16816(acc[mi][nt], ah[mi], bh[nt][0], bh[nt][1]);
                    mma16816(acc[mi][nt], ah[mi], bl[nt][0], bl[nt][1]);
                    mma16816(acc[mi][nt], al[mi], bh[nt][0], bh[nt][1]);
                }
        }
    }

    // ---- epilogue: regs -> smem -> gmem (bias + relu; fp32 and/or bf16 hi/lo) ----
    __syncthreads();
    constexpr int SCS = NBLK + 4;
    float* sC = (float*)dsm;
#pragma unroll
    for (int mi = 0; mi < 2; mi++)
#pragma unroll
        for (int nt = 0; nt < NT; nt++) {
            int r0 = m_off + mi * 16 + (lane >> 2);
            int c0 = n_off + nt * 8 + (lane & 3) * 2;
            *(float2*)&sC[r0 * SCS + c0] = make_float2(acc[mi][nt][0], acc[mi][nt][1]);
            *(float2*)&sC[(r0 + 8) * SCS + c0] = make_float2(acc[mi][nt][2], acc[mi][nt][3]);
        }
    __syncthreads();
#pragma unroll
    for (int i = 0; i < (128 * NBLK) / GTHREADS; i++) {
        int idx = tid + i * GTHREADS;
        int r = idx / NBLK, cc = idx % NBLK;
        int gm = m0 + r, gn = n0 + cc;
        if (gm < NNODES && gn < Nout) {
            float v = fmaxf(sC[r * SCS + cc] + bias[gn], 0.f);
            if (outF) outF[(size_t)gm * Nout + gn] = v;
            if (outHi) {
                __nv_bfloat16 hi = __float2bfloat16(v);
                size_t o = (size_t)gm * strideO + colOff + gn;
                outHi[o] = hi;
                outLo[o] = __float2bfloat16(v - __bfloat162float(hi));
            }
        }
    }
}

// ---------------- final head: logits + log_softmax ----------------
__global__ void logits_kernel(const float* __restrict__ emb,
                              const float* __restrict__ lin2_w,
                              const float* __restrict__ lin2_b,
                              float* __restrict__ out)
{
    int gtid = blockIdx.x * blockDim.x + threadIdx.x;
    int node = gtid >> 5;
    int lane = gtid & 31;
    if (node >= NNODES) return;
    const float* e = emb + (size_t)node * DIM3;
    float s0 = 0.f, s1 = 0.f;
    for (int k = lane; k < DIM3; k += 32) {
        float v = e[k];
        s0 = fmaf(v, lin2_w[2 * k + 0], s0);
        s1 = fmaf(v, lin2_w[2 * k + 1], s1);
    }
#pragma unroll
    for (int o = 16; o; o >>= 1) {
        s0 += __shfl_down_sync(0xffffffffu, s0, o);
        s1 += __shfl_down_sync(0xffffffffu, s1, o);
    }
    if (lane == 0) {
        s0 += lin2_b[0];
        s1 += lin2_b[1];
        float m = fmaxf(s0, s1);
        float l = m + logf(expf(s0 - m) + expf(s1 - m));
        out[2 * node + 0] = s0 - l;
        out[2 * node + 1] = s1 - l;
    }
}

// ---------------- launch ----------------
extern "C" void kernel_launch(void* const* d_in, const int* in_sizes, int n_in,
                              void* d_out, int out_size)
{
    const float* x       = (const float*)d_in[0];
    const float* gene    = (const float*)d_in[1];
    const float* w_rel1  = (const float*)d_in[2];
    const float* root1   = (const float*)d_in[3];
    const float* b1      = (const float*)d_in[4];
    const float* w_rel2  = (const float*)d_in[5];
    const float* root2   = (const float*)d_in[6];
    const float* b2      = (const float*)d_in[7];
    const float* lin1_w  = (const float*)d_in[8];
    const float* lin1_b  = (const float*)d_in[9];
    const float* lin2_w  = (const float*)d_in[10];
    const float* lin2_b  = (const float*)d_in[11];
    const int*   ei = (const int*)d_in[12];
    const int*   et = (const int*)d_in[13];
    float* out = (float*)d_out;

    __nv_bfloat16 *Xch, *Xcl, *W1h, *W1l, *A1ch, *A1cl, *W2h, *W2l, *A2h, *A2l, *W3h, *W3l;
    float *A1;
    cudaGetSymbolAddress((void**)&Xch, g_Xcat_hi);  cudaGetSymbolAddress((void**)&Xcl, g_Xcat_lo);
    cudaGetSymbolAddress((void**)&W1h, g_W1hi);     cudaGetSymbolAddress((void**)&W1l, g_W1lo);
    cudaGetSymbolAddress((void**)&A1, g_A1);
    cudaGetSymbolAddress((void**)&A1ch, g_A1cat_hi); cudaGetSymbolAddress((void**)&A1cl, g_A1cat_lo);
    cudaGetSymbolAddress((void**)&W2h, g_W2hi);     cudaGetSymbolAddress((void**)&W2l, g_W2lo);
    cudaGetSymbolAddress((void**)&A2h, g_A2hi);     cudaGetSymbolAddress((void**)&A2l, g_A2lo);
    cudaGetSymbolAddress((void**)&W3h, g_W3hi);     cudaGetSymbolAddress((void**)&W3l, g_W3lo);

    const int SMEM128 = 3 * (2 * TILE_B + 2 * 128 * 128);   // 192 KB
    const int SMEM64  = 3 * (2 * TILE_B + 2 * 64 * 128);    // 144 KB
    cudaFuncSetAttribute(gemm_mma_kernel<128>, cudaFuncAttributeMaxDynamicSharedMemorySize, SMEM128);
    cudaFuncSetAttribute(gemm_mma_kernel<64>,  cudaFuncAttributeMaxDynamicSharedMemorySize, SMEM64);

    // 1) weight transposes + splits
    {
        dim3 tb(32, 8);
        transpose_split_kernel<<<dim3(KP1 / 32, NP1 / 32, 5), tb>>>(w_rel1, root1, W1h, W1l, IN_DIM, DIM1, KP1, KC1, NP1);
        transpose_split_kernel<<<dim3(KP2 / 32, NP2 / 32, 5), tb>>>(w_rel2, root2, W2h, W2l, DIM1, DIM2, KP2, KC2, NP2);
        transpose_split_kernel<<<dim3(KP3 / 32, NP3 / 32, 1), tb>>>(nullptr, lin1_w, W3h, W3l, DIM2, DIM3, KP3, KP3, NP3);
    }
    // 2) edge preprocessing
    zero_cnt_kernel<<<(NSEG + 255) / 256, 256>>>();
    count_kernel<<<(N_EDGES + 255) / 256, 256>>>(ei, et);
    scan_kernel<<<1, 1024>>>();
    fill_kernel<<<(N_EDGES + 255) / 256, 256>>>(ei, et);

    // 3) layer-1 input assembly
    {
        size_t tot = (size_t)NNODES * IN_DIM;
        xfill_kernel<<<(unsigned)((tot + 255) / 256), 256>>>(x, gene);
    }
    agg_seg_kernel<7><<<NSEG, 256>>>(x, gene, N_DRUGS, IN_DIM, KP1, KC1, Xch, Xcl);

    // 4) layer-1 GEMM (n-tile 128): A1 fp32 + hi/lo into A1cat root slot
    gemm_mma_kernel<128><<<dim3(NP1 / 128, MPAD / 128), GTHREADS, SMEM128>>>(
        Xch, Xcl, W1h, W1l, KC1, DIM1, b1, A1, A1ch, A1cl, KC2, 4 * KP2);

    // 5) layer-2 input assembly
    agg_seg_kernel<6><<<NSEG, 256>>>(A1, A1, NNODES, DIM1, KP2, KC2, A1ch, A1cl);

    // 6) layer-2 GEMM (n-tile 64: less padding, better wave fill)
    gemm_mma_kernel<64><<<dim3(NP2 / 64, MPAD / 128), GTHREADS, SMEM64>>>(
        A1ch, A1cl, W2h, W2l, KC2, DIM2, b2, nullptr, A2h, A2l, KP3, 0);

    // 7) lin1 -> emb in output buffer
    float* emb = out + 2 * NNODES;
    gemm_mma_kernel<128><<<dim3(NP3 / 128, MPAD / 128), GTHREADS, SMEM128>>>(
        A2h, A2l, W3h, W3l, KP3, DIM3, lin1_b, emb, nullptr, nullptr, 0, 0);

    // 8) lin2 + log_softmax
    logits_kernel<<<(NNODES * 32 + 255) / 256, 256>>>(emb, lin2_w, lin2_b, out);
}